// round 11
// baseline (speedup 1.0000x reference)
#include <cuda_runtime.h>
#include <cstdint>

// LeakageNlinCore as dense M=32768, N=128, K=128 tf32 GEMM via mma.sync.
// Round-11: single kernel. B fragments staged in-kernel straight from W with
// reordered loops so LOO index math is 1 compare + 1 predicated add per value
// (j = tg+4m is compile-time affine after unrolling). R10's measured-best
// skeleton otherwise: 256 threads, 2 CTAs/SM, scalar-LDS mainloop,
// double-buffered 32-row tiles, register-resident B.

#define NTHREADS 256
#define TILE_M   32
#define TILES    4
#define ROWS_CTA (TILE_M * TILES)   // 128
#define KDIM     128
#define NOUT     128
#define STRIDE   132                // padded F row stride (floats)

#define FB_FLOATS (TILE_M * STRIDE)          // 4224 per buffer

__device__ __forceinline__ uint32_t f2tf32(float f) {
    uint32_t r;
    asm("cvt.rna.tf32.f32 %0, %1;" : "=r"(r) : "f"(f));
    return r;
}

__device__ __forceinline__ void mma_16x8x8(float& d0, float& d1, float& d2, float& d3,
                                           uint32_t a0, uint32_t a1, uint32_t a2, uint32_t a3,
                                           uint32_t b0, uint32_t b1) {
    asm volatile(
        "mma.sync.aligned.m16n8k8.row.col.f32.tf32.tf32.f32 "
        "{%0,%1,%2,%3}, {%4,%5,%6,%7}, {%8,%9}, {%0,%1,%2,%3};"
        : "+f"(d0), "+f"(d1), "+f"(d2), "+f"(d3)
        : "r"(a0), "r"(a1), "r"(a2), "r"(a3), "r"(b0), "r"(b1));
}

__global__ void __launch_bounds__(NTHREADS, 2)
leakage_kernel(const float* __restrict__ x, const float* __restrict__ W,
               float* __restrict__ out) {
    __shared__ float Fb[2 * FB_FLOATS];   // [2][32][132]

    const int tid = threadIdx.x;
    const int wid = tid >> 5;            // 0..7
    const int lid = tid & 31;
    const int g = lid >> 2;
    const int tg = lid & 3;
    const int cgrp = wid;                // 16-col group (0..7)
    const size_t t0 = (size_t)blockIdx.x * ROWS_CTA;

    // ---- Issue tile-0 x loads FIRST (hide DRAM latency behind b staging) ----
    float4 r[4];
    {
        const float4* xb = (const float4*)(x + t0 * KDIM);
#pragma unroll
        for (int it = 0; it < 4; it++)
            r[it] = xb[(it * 8 + wid) * 32 + lid];
    }

    // ---- B fragments straight from W (L2-resident), minimal index math ----
    // b[nb][ks][h] multiplies F[k], k = ks*8 + tg + 4h, output column
    // n = cgrp*16 + nb*8 + g.  k = half*64 + j with half = ks>>3,
    // j = tg + 4*(2*(ks&7)+h).  Loop over m = 2*(ks&7)+h = 0..15: j = tg+4m
    // is affine in the unrolled index; only (j>c) is runtime.
    float b[2][16][2];
#pragma unroll
    for (int nb = 0; nb < 2; nb++) {
        const int n = cgrp * 16 + nb * 8 + g;
        const int c = n >> 1;
        const float* wrow = W + n * 126;
#pragma unroll
        for (int half = 0; half < 2; half++) {
            const float* wl = wrow + half * 63;
#pragma unroll
            for (int m = 0; m < 16; m++) {
                const int j = tg + 4 * m;
                float v = 0.0f;
                if (j != c) v = wl[j - (j > c)];
                b[nb][(m >> 1) + half * 8][m & 1] = __uint_as_float(f2tf32(v));
            }
        }
    }

#pragma unroll 1
    for (int t = 0; t < TILES; t++) {
        float* buf = Fb + (t & 1) * FB_FLOATS;

        // ---- Transform r -> F (row = it*8+wid, channel pair = lid) ----
#pragma unroll
        for (int it = 0; it < 4; it++) {
            float4 v = r[it];
            float amp0 = v.x * v.x + v.y * v.y;
            float amp1 = v.z * v.z + v.w * v.w;
            uint32_t fr0 = f2tf32(amp0 * v.x), fi0 = f2tf32(amp0 * v.y);
            uint32_t fr1 = f2tf32(amp1 * v.z), fi1 = f2tf32(amp1 * v.w);
            uint32_t* rowp = (uint32_t*)(buf + (it * 8 + wid) * STRIDE);
            int c0 = lid * 2;
            *(uint2*)(rowp + c0) = make_uint2(fr0, fr1);        // fr -> [0,64)
            *(uint2*)(rowp + 64 + c0) = make_uint2(fi0, fi1);   // fi -> [64,128)
        }
        __syncthreads();

        // ---- Prefetch next tile's globals (hidden behind mainloop) ----
        if (t + 1 < TILES) {
            const float4* xb = (const float4*)(x + (t0 + (size_t)(t + 1) * TILE_M) * KDIM);
#pragma unroll
            for (int it = 0; it < 4; it++)
                r[it] = xb[(it * 8 + wid) * 32 + lid];
        }

        // ---- Mainloop: all 32 tile rows x cols [cgrp*16,+16) ----
        float acc[2][2][4];
#pragma unroll
        for (int mt = 0; mt < 2; mt++)
#pragma unroll
            for (int nb = 0; nb < 2; nb++)
#pragma unroll
                for (int q = 0; q < 4; q++) acc[mt][nb][q] = 0.0f;

        const uint32_t* F = (const uint32_t*)buf;
#pragma unroll
        for (int ks = 0; ks < 16; ks++) {
            const int k0 = ks * 8 + tg;
            uint32_t a[2][4];
#pragma unroll
            for (int mt = 0; mt < 2; mt++) {
                const uint32_t* f0 = F + (mt * 16 + g) * STRIDE + k0;
                const uint32_t* f1 = F + (mt * 16 + g + 8) * STRIDE + k0;
                a[mt][0] = f0[0];
                a[mt][1] = f1[0];
                a[mt][2] = f0[4];
                a[mt][3] = f1[4];
            }
            uint32_t b00 = __float_as_uint(b[0][ks][0]);
            uint32_t b01 = __float_as_uint(b[0][ks][1]);
            uint32_t b10 = __float_as_uint(b[1][ks][0]);
            uint32_t b11 = __float_as_uint(b[1][ks][1]);
#pragma unroll
            for (int mt = 0; mt < 2; mt++) {
                mma_16x8x8(acc[mt][0][0], acc[mt][0][1], acc[mt][0][2], acc[mt][0][3],
                           a[mt][0], a[mt][1], a[mt][2], a[mt][3], b00, b01);
                mma_16x8x8(acc[mt][1][0], acc[mt][1][1], acc[mt][1][2], acc[mt][1][3],
                           a[mt][0], a[mt][1], a[mt][2], a[mt][3], b10, b11);
            }
        }

        // ---- Epilogue: store warp slice ----
        const size_t rbase = t0 + (size_t)t * TILE_M;
#pragma unroll
        for (int mt = 0; mt < 2; mt++) {
#pragma unroll
            for (int nb = 0; nb < 2; nb++) {
                const int col = cgrp * 16 + nb * 8 + tg * 2;
                float* o0 = out + (rbase + mt * 16 + g) * NOUT + col;
                *(float2*)o0 = make_float2(acc[mt][nb][0], acc[mt][nb][1]);
                *(float2*)(o0 + 8 * NOUT) = make_float2(acc[mt][nb][2], acc[mt][nb][3]);
            }
        }
        // Next transform writes the other buffer; the sync at the top of the
        // next iteration orders reuse of this one.
        __syncthreads();
    }
}

extern "C" void kernel_launch(void* const* d_in, const int* in_sizes, int n_in,
                              void* d_out, int out_size) {
    const float* x = (const float*)d_in[0];  // [B,S,C,2] fp32
    const float* W = (const float*)d_in[1];  // [C,2,126] fp32
    float* out = (float*)d_out;              // [B,S,C,2] fp32

    int tokens = in_sizes[0] / KDIM;         // 32768
    int nblocks = tokens / ROWS_CTA;         // 256

    leakage_kernel<<<nblocks, NTHREADS>>>(x, W, out);
}

// round 12
// speedup vs baseline: 1.3233x; 1.3233x over previous
#include <cuda_runtime.h>
#include <cuda_fp16.h>
#include <cstdint>

// LeakageNlinCore as dense M=32768, N=128, K=128 GEMM via fp16 mma.m16n8k16
// (fp16 mantissa == tf32 mantissa; fp32 accumulate -> same ~3e-4 rel err).
// R10 skeleton: 256-thread CTAs, 2 CTAs/SM, double-buffered 32-row tiles,
// register-resident B from a fragment-ordered pre-packed global.

#define NTHREADS 256
#define TILE_M   32
#define TILES    4
#define ROWS_CTA (TILE_M * TILES)   // 128
#define KDIM     128
#define NOUT     128
#define ST       68                 // F row stride in u32 (fp16x2 pairs + pad)

#define FB_U32 (TILE_M * ST)        // 2176 per buffer

// Fragment-ordered packed G (fp16x2): [cgrp(8)][j4(8)][lane(32)] uint4
// j = j4*4+e encodes (nb = j>>4, ks = (j>>1)&7, hb = j&1):
//   n = cgrp*16 + nb*8 + g,  k0 = 16*ks + 2*tg + 8*hb, pair (k0, k0+1)
__device__ uint4 Gpack16[8 * 8 * 32];

__device__ __forceinline__ uint32_t pack_h2(float lo, float hi) {
    __half2 h = __float22half2_rn(make_float2(lo, hi));
    return *(uint32_t*)&h;
}

__device__ __forceinline__ void mma_16x8x16(float& d0, float& d1, float& d2, float& d3,
                                            uint32_t a0, uint32_t a1, uint32_t a2, uint32_t a3,
                                            uint32_t b0, uint32_t b1) {
    asm volatile(
        "mma.sync.aligned.m16n8k16.row.col.f32.f16.f16.f32 "
        "{%0,%1,%2,%3}, {%4,%5,%6,%7}, {%8,%9}, {%0,%1,%2,%3};"
        : "+f"(d0), "+f"(d1), "+f"(d2), "+f"(d3)
        : "r"(a0), "r"(a1), "r"(a2), "r"(a3), "r"(b0), "r"(b1));
}

// ---- Pre-kernel: LOO-expand W into fragment-ordered fp16x2 Gpack16 -------
__global__ void g_pack_kernel(const float* __restrict__ W) {
    int idx = blockIdx.x * blockDim.x + threadIdx.x;   // 0..2047
    int cgrp = idx >> 8;
    int j4 = (idx >> 5) & 7;
    int lane = idx & 31;
    int g = lane >> 2, tg = lane & 3;
    uint32_t pv[4];
#pragma unroll
    for (int e = 0; e < 4; e++) {
        int j = j4 * 4 + e;
        int nb = j >> 4, ks = (j >> 1) & 7, hb = j & 1;
        int n = cgrp * 16 + nb * 8 + g;
        int c = n >> 1;
        int k0 = 16 * ks + 2 * tg + 8 * hb;
        float v[2];
#pragma unroll
        for (int u = 0; u < 2; u++) {
            int k = k0 + u;
            int jj = k & 63, half = k >> 6;
            float gg = 0.0f;
            if (jj != c) gg = W[n * 126 + half * 63 + jj - (jj > c)];
            v[u] = gg;
        }
        pv[e] = pack_h2(v[0], v[1]);
    }
    Gpack16[idx] = make_uint4(pv[0], pv[1], pv[2], pv[3]);
}

// ---- Main kernel ----------------------------------------------------------
__global__ void __launch_bounds__(NTHREADS, 2)
leakage_main_kernel(const float* __restrict__ x, float* __restrict__ out) {
    __shared__ uint32_t Fb[2 * FB_U32];   // [2][32][ST] fp16x2 pairs

    const int tid = threadIdx.x;
    const int wid = tid >> 5;            // 0..7
    const int lid = tid & 31;
    const int g = lid >> 2;
    const int tg = lid & 3;
    const int cgrp = wid;                // 16-col group
    const size_t t0 = (size_t)blockIdx.x * ROWS_CTA;

    // ---- Issue tile-0 x loads first ----
    float4 r[4];
    {
        const float4* xb = (const float4*)(x + t0 * KDIM);
#pragma unroll
        for (int it = 0; it < 4; it++)
            r[it] = xb[(it * 8 + wid) * 32 + lid];
    }

    // ---- B slice: 32 fp16x2 regs via 8 coalesced LDG.128 ----
    uint32_t b[2][8][2];
    {
        const uint4* gp = Gpack16 + cgrp * 256 + lid;
#pragma unroll
        for (int j4 = 0; j4 < 8; j4++) {
            uint4 q = gp[j4 * 32];
#pragma unroll
            for (int e = 0; e < 4; e++) {
                const int j = j4 * 4 + e;
                const int nb = j >> 4, ks = (j >> 1) & 7, hb = j & 1;
                uint32_t val = (e == 0) ? q.x : (e == 1) ? q.y : (e == 2) ? q.z : q.w;
                b[nb][ks][hb] = val;
            }
        }
    }

#pragma unroll 1
    for (int t = 0; t < TILES; t++) {
        uint32_t* buf = Fb + (t & 1) * FB_U32;

        // ---- Transform r -> F (fp16x2), conflict-free STS.32 ----
        // row = it*8+wid; channel pair (2*lid, 2*lid+1):
        // fr pair -> P[row][lid], fi pair -> P[row][32+lid]
#pragma unroll
        for (int it = 0; it < 4; it++) {
            float4 v = r[it];
            float amp0 = v.x * v.x + v.y * v.y;
            float amp1 = v.z * v.z + v.w * v.w;
            uint32_t frp = pack_h2(amp0 * v.x, amp1 * v.z);
            uint32_t fip = pack_h2(amp0 * v.y, amp1 * v.w);
            uint32_t* rowp = buf + (it * 8 + wid) * ST;
            rowp[lid] = frp;
            rowp[32 + lid] = fip;
        }
        __syncthreads();

        // ---- Prefetch next tile's globals ----
        if (t + 1 < TILES) {
            const float4* xb = (const float4*)(x + (t0 + (size_t)(t + 1) * TILE_M) * KDIM);
#pragma unroll
            for (int it = 0; it < 4; it++)
                r[it] = xb[(it * 8 + wid) * 32 + lid];
        }

        // ---- Mainloop: 32 rows x 16 cols, 8 k-chunks of 16 ----
        float acc[2][2][4];
#pragma unroll
        for (int mt = 0; mt < 2; mt++)
#pragma unroll
            for (int nb = 0; nb < 2; nb++)
#pragma unroll
                for (int q = 0; q < 4; q++) acc[mt][nb][q] = 0.0f;

        const uint32_t* f0 = buf + g * ST + tg;
        const uint32_t* f1 = buf + (g + 8) * ST + tg;
        const uint32_t* f2 = buf + (g + 16) * ST + tg;
        const uint32_t* f3 = buf + (g + 24) * ST + tg;

#pragma unroll
        for (int ks = 0; ks < 8; ks++) {
            const int off = 8 * ks;
            uint32_t a00 = f0[off],     a01 = f1[off];
            uint32_t a02 = f0[off + 4], a03 = f1[off + 4];
            uint32_t a10 = f2[off],     a11 = f3[off];
            uint32_t a12 = f2[off + 4], a13 = f3[off + 4];
            mma_16x8x16(acc[0][0][0], acc[0][0][1], acc[0][0][2], acc[0][0][3],
                        a00, a01, a02, a03, b[0][ks][0], b[0][ks][1]);
            mma_16x8x16(acc[0][1][0], acc[0][1][1], acc[0][1][2], acc[0][1][3],
                        a00, a01, a02, a03, b[1][ks][0], b[1][ks][1]);
            mma_16x8x16(acc[1][0][0], acc[1][0][1], acc[1][0][2], acc[1][0][3],
                        a10, a11, a12, a13, b[0][ks][0], b[0][ks][1]);
            mma_16x8x16(acc[1][1][0], acc[1][1][1], acc[1][1][2], acc[1][1][3],
                        a10, a11, a12, a13, b[1][ks][0], b[1][ks][1]);
        }

        // ---- Epilogue: store warp slice ----
        const size_t rbase = t0 + (size_t)t * TILE_M;
#pragma unroll
        for (int mt = 0; mt < 2; mt++) {
#pragma unroll
            for (int nb = 0; nb < 2; nb++) {
                const int col = cgrp * 16 + nb * 8 + tg * 2;
                float* o0 = out + (rbase + mt * 16 + g) * NOUT + col;
                *(float2*)o0 = make_float2(acc[mt][nb][0], acc[mt][nb][1]);
                *(float2*)(o0 + 8 * NOUT) = make_float2(acc[mt][nb][2], acc[mt][nb][3]);
            }
        }
        __syncthreads();
    }
}

extern "C" void kernel_launch(void* const* d_in, const int* in_sizes, int n_in,
                              void* d_out, int out_size) {
    const float* x = (const float*)d_in[0];  // [B,S,C,2] fp32
    const float* W = (const float*)d_in[1];  // [C,2,126] fp32
    float* out = (float*)d_out;              // [B,S,C,2] fp32

    int tokens = in_sizes[0] / KDIM;         // 32768
    int nblocks = tokens / ROWS_CTA;         // 256

    g_pack_kernel<<<32, 64>>>(W);
    leakage_main_kernel<<<nblocks, NTHREADS>>>(x, out);
}